// round 1
// baseline (speedup 1.0000x reference)
#include <cuda_runtime.h>
#include <math.h>

// Problem constants
// B=32, S=1024, T=512, SRC=1024, TGT=1024, OUT=1024, H=8, dh=128

#define BM 128
#define BN 128
#define BK 16

// ---------------- scratch (static __device__ — no allocation) ----------------
__device__ float d_scales[4];
__device__ float d_partial[3][256];
__device__ float d_src_trans[(size_t)32 * 1024 * 2048];   // [B*S, 2048]
__device__ float d_tgt_trans[(size_t)32 * 512 * 1024];    // [B*T, 1024]
__device__ float d_tgt_update[(size_t)32 * 512 * 1024];   // [B*T, 1024]
__device__ float d_scores[(size_t)32 * 8 * 512 * 1024];   // [B,H,T,S]

// ---------------- weight-norm scale reductions (deterministic 2-pass) --------
__global__ void sumsq_partial(const float* __restrict__ v0, int n0,
                              const float* __restrict__ v1, int n1,
                              const float* __restrict__ v2, int n2) {
    int t = blockIdx.y;
    const float* v = (t == 0) ? v0 : (t == 1) ? v1 : v2;
    int n = (t == 0) ? n0 : (t == 1) ? n1 : n2;
    float s = 0.f;
    for (int i = blockIdx.x * blockDim.x + threadIdx.x; i < n; i += gridDim.x * blockDim.x) {
        float x = v[i];
        s += x * x;
    }
    __shared__ float sm[256];
    sm[threadIdx.x] = s;
    __syncthreads();
    for (int o = 128; o > 0; o >>= 1) {
        if (threadIdx.x < o) sm[threadIdx.x] += sm[threadIdx.x + o];
        __syncthreads();
    }
    if (threadIdx.x == 0) d_partial[t][blockIdx.x] = sm[0];
}

__global__ void finalize_scales(const float* __restrict__ g0,
                                const float* __restrict__ g1,
                                const float* __restrict__ g2) {
    int t = blockIdx.x;
    __shared__ float sm[256];
    sm[threadIdx.x] = d_partial[t][threadIdx.x];
    __syncthreads();
    for (int o = 128; o > 0; o >>= 1) {
        if (threadIdx.x < o) sm[threadIdx.x] += sm[threadIdx.x + o];
        __syncthreads();
    }
    if (threadIdx.x == 0) {
        float g = (t == 0) ? *g0 : (t == 1) ? *g1 : *g2;
        d_scales[t] = g / sqrtf(sm[0]);
    }
}

// ---------------- generic batched 128x128x16 SGEMM ---------------------------
// C[M,N] = epilogue( scale * (A @ B^T or A @ B) )
// A2 != null: virtual concat along K at splitK (same lda).
// mode 0: v = s*acc (+bias[col]) (*mask[row])     mode 1: v = s*acc; mask[col]==0 -> -1e30
// z-batch: offX = (z/Hz)*zXb + (z%Hz)*zXh
__global__ void __launch_bounds__(256)
gemm128(const float* __restrict__ A, const float* __restrict__ A2,
        const float* __restrict__ Bm, float* __restrict__ C,
        const float* __restrict__ bias, const float* __restrict__ mask,
        float scaleMul, int scaleIdx,
        int M, int N, int K, int splitK,
        int lda, int ldb, int ldc,
        int Hz,
        long zAb, long zAh, long zBb, long zBh, long zCb, long zCh, long zMb,
        int bTrans, int mode) {
    __shared__ float As[BK][BM];
    __shared__ float Bs[BK][BN];

    int z = blockIdx.z;
    int zb = z / Hz, zh = z - zb * Hz;
    A += (size_t)zb * zAb + (size_t)zh * zAh;
    if (A2) A2 += (size_t)zb * zAb + (size_t)zh * zAh;  // unused when batched
    Bm += (size_t)zb * zBb + (size_t)zh * zBh;
    C += (size_t)zb * zCb + (size_t)zh * zCh;
    size_t maskOff = (size_t)zb * (size_t)zMb;

    int tid = threadIdx.x;
    int rowBase = blockIdx.y * BM;
    int colBase = blockIdx.x * BN;

    int lr = tid >> 1;
    int lc = (tid & 1) * 8;
    int bkr = tid >> 4;  // for bTrans==0
    int bc4 = tid & 15;

    float acc[8][8];
#pragma unroll
    for (int i = 0; i < 8; i++)
#pragma unroll
        for (int j = 0; j < 8; j++) acc[i][j] = 0.f;

    int tr = tid >> 4, tc = tid & 15;

    for (int k0 = 0; k0 < K; k0 += BK) {
        // ---- load A tile [128, 16] ----
        {
            int kg = k0 + lc;
            const float* ap;
            if (A2 != nullptr && kg >= splitK)
                ap = A2 + (size_t)(rowBase + lr) * lda + (kg - splitK);
            else
                ap = A + (size_t)(rowBase + lr) * lda + kg;
            float4 a0 = *(const float4*)ap;
            float4 a1 = *(const float4*)(ap + 4);
            As[lc + 0][lr] = a0.x; As[lc + 1][lr] = a0.y;
            As[lc + 2][lr] = a0.z; As[lc + 3][lr] = a0.w;
            As[lc + 4][lr] = a1.x; As[lc + 5][lr] = a1.y;
            As[lc + 6][lr] = a1.z; As[lc + 7][lr] = a1.w;
        }
        // ---- load B tile ----
        if (bTrans) {  // B[N,K] row-major
            const float* bp = Bm + (size_t)(colBase + lr) * ldb + k0 + lc;
            float4 b0 = *(const float4*)bp;
            float4 b1 = *(const float4*)(bp + 4);
            Bs[lc + 0][lr] = b0.x; Bs[lc + 1][lr] = b0.y;
            Bs[lc + 2][lr] = b0.z; Bs[lc + 3][lr] = b0.w;
            Bs[lc + 4][lr] = b1.x; Bs[lc + 5][lr] = b1.y;
            Bs[lc + 6][lr] = b1.z; Bs[lc + 7][lr] = b1.w;
        } else {  // B[K,N] row-major
            const float* bp = Bm + (size_t)(k0 + bkr) * ldb + colBase;
            float4 b0 = *(const float4*)(bp + bc4 * 4);
            float4 b1 = *(const float4*)(bp + bc4 * 4 + 64);
            ((float4*)Bs[bkr])[bc4] = b0;
            ((float4*)Bs[bkr])[bc4 + 16] = b1;
        }
        __syncthreads();
#pragma unroll
        for (int kk = 0; kk < BK; kk++) {
            float4 a0 = ((float4*)&As[kk][tr * 8])[0];
            float4 a1 = ((float4*)&As[kk][tr * 8])[1];
            float4 b0 = ((float4*)&Bs[kk][tc * 8])[0];
            float4 b1 = ((float4*)&Bs[kk][tc * 8])[1];
            float a[8] = {a0.x, a0.y, a0.z, a0.w, a1.x, a1.y, a1.z, a1.w};
            float b[8] = {b0.x, b0.y, b0.z, b0.w, b1.x, b1.y, b1.z, b1.w};
#pragma unroll
            for (int i = 0; i < 8; i++)
#pragma unroll
                for (int j = 0; j < 8; j++) acc[i][j] += a[i] * b[j];
        }
        __syncthreads();
    }

    float s = scaleMul * (scaleIdx >= 0 ? d_scales[scaleIdx] : 1.0f);
#pragma unroll
    for (int i = 0; i < 8; i++) {
        int r = rowBase + tr * 8 + i;
        float rowm = (mode == 0 && mask) ? mask[maskOff + r] : 1.0f;
        float o[8];
#pragma unroll
        for (int j = 0; j < 8; j++) {
            int c = colBase + tc * 8 + j;
            float v = acc[i][j] * s;
            if (bias) v += bias[c];
            if (mode == 0) {
                v *= rowm;
            } else {
                if (mask[maskOff + c] == 0.f) v = -1e30f;
            }
            o[j] = v;
        }
        float4* cp = (float4*)(C + (size_t)r * ldc + colBase + tc * 8);
        cp[0] = make_float4(o[0], o[1], o[2], o[3]);
        cp[1] = make_float4(o[4], o[5], o[6], o[7]);
    }
}

// ---------------- softmax over last dim (1024), warp per row -----------------
__global__ void softmax1024(float* __restrict__ s) {
    int warp = threadIdx.x >> 5, lane = threadIdx.x & 31;
    size_t row = (size_t)blockIdx.x * 8 + warp;
    float4* p = (float4*)(s + row * 1024);
    float4 v[8];
    float mx = -3.4e38f;
#pragma unroll
    for (int i = 0; i < 8; i++) {
        v[i] = p[i * 32 + lane];
        mx = fmaxf(mx, fmaxf(fmaxf(v[i].x, v[i].y), fmaxf(v[i].z, v[i].w)));
    }
#pragma unroll
    for (int o = 16; o > 0; o >>= 1) mx = fmaxf(mx, __shfl_xor_sync(0xffffffffu, mx, o));
    float sum = 0.f;
#pragma unroll
    for (int i = 0; i < 8; i++) {
        v[i].x = __expf(v[i].x - mx);
        v[i].y = __expf(v[i].y - mx);
        v[i].z = __expf(v[i].z - mx);
        v[i].w = __expf(v[i].w - mx);
        sum += v[i].x + v[i].y + v[i].z + v[i].w;
    }
#pragma unroll
    for (int o = 16; o > 0; o >>= 1) sum += __shfl_xor_sync(0xffffffffu, sum, o);
    float inv = 1.f / sum;
#pragma unroll
    for (int i = 0; i < 8; i++) {
        v[i].x *= inv; v[i].y *= inv; v[i].z *= inv; v[i].w *= inv;
        p[i * 32 + lane] = v[i];
    }
}

// ---------------- launch ------------------------------------------------------
extern "C" void kernel_launch(void* const* d_in, const int* in_sizes, int n_in,
                              void* d_out, int out_size) {
    const float* src = (const float*)d_in[0];
    const float* tgt = (const float*)d_in[1];
    const float* src_mask = (const float*)d_in[2];
    const float* tgt_mask = (const float*)d_in[3];
    const float* v_src = (const float*)d_in[4];
    const float* g_src = (const float*)d_in[5];
    const float* b_src = (const float*)d_in[6];
    const float* v_tgt = (const float*)d_in[7];
    const float* g_tgt = (const float*)d_in[8];
    const float* b_tgt = (const float*)d_in[9];
    const float* v_out = (const float*)d_in[10];
    const float* g_out = (const float*)d_in[11];
    const float* b_out = (const float*)d_in[12];
    float* out = (float*)d_out;

    void *p0, *p1, *p2, *p3;
    cudaGetSymbolAddress(&p0, d_src_trans);
    cudaGetSymbolAddress(&p1, d_tgt_trans);
    cudaGetSymbolAddress(&p2, d_tgt_update);
    cudaGetSymbolAddress(&p3, d_scores);
    float* st = (float*)p0;
    float* tt = (float*)p1;
    float* tu = (float*)p2;
    float* sc = (float*)p3;

    const long TS = (long)512 * 1024;  // per-(b,h) score block

    // weight-norm scales
    sumsq_partial<<<dim3(256, 3), 256>>>(v_src, 2048 * 1024, v_tgt, 1024 * 1024, v_out, 1024 * 2048);
    finalize_scales<<<3, 256>>>(g_src, g_tgt, g_out);

    // GEMM1: src_trans[B*S,2048] = mask_row * (src @ (s*v_src)^T + b_src)
    gemm128<<<dim3(2048 / BN, 32768 / BM, 1), 256>>>(
        src, nullptr, v_src, st, b_src, src_mask,
        1.0f, 0,
        32768, 2048, 1024, 0,
        1024, 1024, 2048,
        1, 0, 0, 0, 0, 0, 0, 0,
        1, 0);

    // GEMM2: tgt_trans[B*T,1024] = mask_row * (tgt @ (s*v_tgt)^T + b_tgt)
    gemm128<<<dim3(1024 / BN, 16384 / BM, 1), 256>>>(
        tgt, nullptr, v_tgt, tt, b_tgt, tgt_mask,
        1.0f, 1,
        16384, 1024, 1024, 0,
        1024, 1024, 1024,
        1, 0, 0, 0, 0, 0, 0, 0,
        1, 0);

    // scores[B,H,T,S] = (q @ k^T)/sqrt(128), col-masked to -1e30
    gemm128<<<dim3(1024 / BN, 512 / BM, 256), 256>>>(
        tt, nullptr, st, sc, nullptr, src_mask,
        0.08838834764831845f, -1,
        512, 1024, 128, 0,
        1024, 2048, 1024,
        8,
        (long)512 * 1024, 128,            // A: tgt_trans  b*T*1024 + h*128
        (long)1024 * 2048, 128,           // B: src_key    b*S*2048 + h*128
        8 * TS, TS,                       // C: scores     z*T*S
        1024,                             // mask stride per batch
        1, 1);

    // softmax over S
    softmax1024<<<131072 / 8, 256>>>(sc);

    // PV: tgt_update[b,t,h*128+d] = P[b,h,t,:] @ V[b,:,h,d]
    gemm128<<<dim3(1, 512 / BM, 256), 256>>>(
        sc, nullptr, st + 1024, tu, nullptr, nullptr,
        1.0f, -1,
        512, 128, 1024, 0,
        1024, 2048, 1024,
        8,
        8 * TS, TS,                       // A: scores z*T*S
        (long)1024 * 2048, 128,           // B: src_val b*S*2048 + 1024 + h*128
        (long)512 * 1024, 128,            // C: tgt_update b*T*1024 + h*128
        0,
        0, 0);

    // GEMM3: out = [tgt | tgt_update] @ (s*v_out)^T + b_out
    gemm128<<<dim3(1024 / BN, 16384 / BM, 1), 256>>>(
        tgt, tu, v_out, out, b_out, nullptr,
        1.0f, 2,
        16384, 1024, 2048, 1024,
        1024, 2048, 1024,
        1, 0, 0, 0, 0, 0, 0, 0,
        1, 0);
}

// round 3
// speedup vs baseline: 2.1447x; 2.1447x over previous
#include <cuda_runtime.h>
#include <cuda_bf16.h>
#include <math.h>
#include <stdint.h>

// B=32, S=1024, T=512, SRC=TGT=OUT=1024, H=8, dh=128
// All GEMMs on HMMA (mma.sync bf16 m16n8k16) with 2-way split, 3 products, fp32 accum.

// ======================= helpers =======================
__device__ __forceinline__ uint32_t smem_u32(const void* p) {
    uint32_t a;
    asm("{ .reg .u64 t; cvta.to.shared.u64 t, %1; cvt.u32.u64 %0, t; }" : "=r"(a) : "l"(p));
    return a;
}

#define LDM4(d0, d1, d2, d3, addr)                                             \
    asm volatile("ldmatrix.sync.aligned.m8n8.x4.shared.b16 {%0,%1,%2,%3}, [%4];" \
                 : "=r"(d0), "=r"(d1), "=r"(d2), "=r"(d3) : "r"(addr))

#define MMA(c, a, b)                                                           \
    asm volatile(                                                              \
        "mma.sync.aligned.m16n8k16.row.col.f32.bf16.bf16.f32 "                 \
        "{%0,%1,%2,%3},{%4,%5,%6,%7},{%8,%9},{%0,%1,%2,%3};"                   \
        : "+f"((c)[0]), "+f"((c)[1]), "+f"((c)[2]), "+f"((c)[3])               \
        : "r"((a)[0]), "r"((a)[1]), "r"((a)[2]), "r"((a)[3]),                  \
          "r"((b)[0]), "r"((b)[1]))

// ======================= scratch (static __device__) =======================
__device__ float d_scales[4];
__device__ float d_partial[3][256];

__device__ __nv_bfloat16 s_src_h[(size_t)32768 * 1024], s_src_l[(size_t)32768 * 1024];
__device__ __nv_bfloat16 s_tgt_h[(size_t)16384 * 1024], s_tgt_l[(size_t)16384 * 1024];
__device__ __nv_bfloat16 s_vsrc_h[(size_t)2048 * 1024], s_vsrc_l[(size_t)2048 * 1024];
__device__ __nv_bfloat16 s_vtgt_h[(size_t)1024 * 1024], s_vtgt_l[(size_t)1024 * 1024];
__device__ __nv_bfloat16 s_vout_h[(size_t)1024 * 2048], s_vout_l[(size_t)1024 * 2048];
__device__ float d_st[(size_t)32768 * 2048];   // src_trans fp32
__device__ __nv_bfloat16 s_key_h[(size_t)32768 * 1024], s_key_l[(size_t)32768 * 1024];
__device__ __nv_bfloat16 s_vt_h[(size_t)32 * 1024 * 1024], s_vt_l[(size_t)32 * 1024 * 1024]; // [B][1024(h,d)][S]
__device__ float d_tt[(size_t)16384 * 1024];   // tgt_trans fp32
__device__ __nv_bfloat16 s_q_h[(size_t)16384 * 1024], s_q_l[(size_t)16384 * 1024];
__device__ float d_sc[(size_t)131072 * 1024];  // scores fp32 [B,H,T,S]
__device__ __nv_bfloat16 s_p_h[(size_t)131072 * 1024], s_p_l[(size_t)131072 * 1024];
__device__ float d_tu[(size_t)16384 * 1024];   // tgt_update fp32
__device__ __nv_bfloat16 s_tu_h[(size_t)16384 * 1024], s_tu_l[(size_t)16384 * 1024];

// ======================= weight-norm scales =======================
__global__ void sumsq_partial(const float* __restrict__ v0, int n0,
                              const float* __restrict__ v1, int n1,
                              const float* __restrict__ v2, int n2) {
    int t = blockIdx.y;
    const float* v = (t == 0) ? v0 : (t == 1) ? v1 : v2;
    int n = (t == 0) ? n0 : (t == 1) ? n1 : n2;
    float s = 0.f;
    for (int i = blockIdx.x * blockDim.x + threadIdx.x; i < n; i += gridDim.x * blockDim.x) {
        float x = v[i];
        s += x * x;
    }
    __shared__ float sm[256];
    sm[threadIdx.x] = s;
    __syncthreads();
    for (int o = 128; o > 0; o >>= 1) {
        if (threadIdx.x < o) sm[threadIdx.x] += sm[threadIdx.x + o];
        __syncthreads();
    }
    if (threadIdx.x == 0) d_partial[t][blockIdx.x] = sm[0];
}

__global__ void finalize_scales(const float* __restrict__ g0,
                                const float* __restrict__ g1,
                                const float* __restrict__ g2) {
    int t = blockIdx.x;
    __shared__ float sm[256];
    sm[threadIdx.x] = d_partial[t][threadIdx.x];
    __syncthreads();
    for (int o = 128; o > 0; o >>= 1) {
        if (threadIdx.x < o) sm[threadIdx.x] += sm[threadIdx.x + o];
        __syncthreads();
    }
    if (threadIdx.x == 0) {
        float g = (t == 0) ? *g0 : (t == 1) ? *g1 : *g2;
        d_scales[t] = g / sqrtf(sm[0]);
    }
}

// ======================= fp32 -> bf16 hi/lo split =======================
__global__ void split2(const float* __restrict__ in, __nv_bfloat16* __restrict__ oh,
                       __nv_bfloat16* __restrict__ ol, int cols4, int pitchIn4) {
    size_t r = blockIdx.y;
    const float4* ip = (const float4*)in + r * pitchIn4;
    uint2* ph = (uint2*)oh + r * cols4;
    uint2* pl = (uint2*)ol + r * cols4;
    for (int c = blockIdx.x * blockDim.x + threadIdx.x; c < cols4; c += gridDim.x * blockDim.x) {
        float4 v = ip[c];
        __nv_bfloat162 h01 = __floats2bfloat162_rn(v.x, v.y);
        __nv_bfloat162 h23 = __floats2bfloat162_rn(v.z, v.w);
        float2 f01 = __bfloat1622float2(h01);
        float2 f23 = __bfloat1622float2(h23);
        __nv_bfloat162 l01 = __floats2bfloat162_rn(v.x - f01.x, v.y - f01.y);
        __nv_bfloat162 l23 = __floats2bfloat162_rn(v.z - f23.x, v.w - f23.y);
        uint2 H, L;
        H.x = *reinterpret_cast<unsigned*>(&h01);
        H.y = *reinterpret_cast<unsigned*>(&h23);
        L.x = *reinterpret_cast<unsigned*>(&l01);
        L.y = *reinterpret_cast<unsigned*>(&l23);
        ph[c] = H;
        pl[c] = L;
    }
}

// transpose+split of val half of src_trans: out[b][c][s] = st[b*1024+s][1024+c]
__global__ void splitValT(const float* __restrict__ st,
                          __nv_bfloat16* __restrict__ vh, __nv_bfloat16* __restrict__ vl) {
    __shared__ float t[32][33];
    int b = blockIdx.z;
    int s0 = blockIdx.x * 32, c0 = blockIdx.y * 32;
    int tx = threadIdx.x;
    for (int ty = threadIdx.y; ty < 32; ty += 8)
        t[ty][tx] = st[((size_t)(b * 1024 + s0 + ty)) * 2048 + 1024 + c0 + tx];
    __syncthreads();
    for (int ty = threadIdx.y; ty < 32; ty += 8) {
        float v = t[tx][ty];
        __nv_bfloat16 h = __float2bfloat16_rn(v);
        size_t o = ((size_t)(b * 1024 + c0 + ty)) * 1024 + s0 + tx;
        vh[o] = h;
        vl[o] = __float2bfloat16_rn(v - __bfloat162float(h));
    }
}

// ======================= softmax (1024) fused with bf16 split =======================
__global__ void softmax_split(const float* __restrict__ s,
                              __nv_bfloat16* __restrict__ ph, __nv_bfloat16* __restrict__ pl) {
    int warp = threadIdx.x >> 5, lane = threadIdx.x & 31;
    size_t row = (size_t)blockIdx.x * 8 + warp;
    const float4* p = (const float4*)(s + row * 1024);
    float4 v[8];
    float mx = -3.4e38f;
#pragma unroll
    for (int i = 0; i < 8; i++) {
        v[i] = p[i * 32 + lane];
        mx = fmaxf(mx, fmaxf(fmaxf(v[i].x, v[i].y), fmaxf(v[i].z, v[i].w)));
    }
#pragma unroll
    for (int o = 16; o > 0; o >>= 1) mx = fmaxf(mx, __shfl_xor_sync(0xffffffffu, mx, o));
    float sum = 0.f;
#pragma unroll
    for (int i = 0; i < 8; i++) {
        v[i].x = __expf(v[i].x - mx);
        v[i].y = __expf(v[i].y - mx);
        v[i].z = __expf(v[i].z - mx);
        v[i].w = __expf(v[i].w - mx);
        sum += v[i].x + v[i].y + v[i].z + v[i].w;
    }
#pragma unroll
    for (int o = 16; o > 0; o >>= 1) sum += __shfl_xor_sync(0xffffffffu, sum, o);
    float inv = 1.f / sum;
    uint2* oh = (uint2*)(ph + row * 1024);
    uint2* ol = (uint2*)(pl + row * 1024);
#pragma unroll
    for (int i = 0; i < 8; i++) {
        float a = v[i].x * inv, b = v[i].y * inv, c = v[i].z * inv, d = v[i].w * inv;
        __nv_bfloat162 h01 = __floats2bfloat162_rn(a, b);
        __nv_bfloat162 h23 = __floats2bfloat162_rn(c, d);
        float2 f01 = __bfloat1622float2(h01);
        float2 f23 = __bfloat1622float2(h23);
        __nv_bfloat162 l01 = __floats2bfloat162_rn(a - f01.x, b - f01.y);
        __nv_bfloat162 l23 = __floats2bfloat162_rn(c - f23.x, d - f23.y);
        uint2 H, L;
        H.x = *reinterpret_cast<unsigned*>(&h01);
        H.y = *reinterpret_cast<unsigned*>(&h23);
        L.x = *reinterpret_cast<unsigned*>(&l01);
        L.y = *reinterpret_cast<unsigned*>(&l23);
        oh[i * 32 + lane] = H;
        ol[i * 32 + lane] = L;
    }
}

// ======================= HMMA split-bf16 GEMM =======================
// CTA tile 128x128, 8 warps (2x4), warp tile 64x32. K staged at 64.
// SMEM per stage: Ah 16K | Al 16K | Bh 16K | Bl 16K = 64KB; x2 stages = 128KB.
// SMEM tile layout: [row][64 k] bf16, 128B/row, 16B chunks XOR-swizzled: chunk' = ch ^ (row&7).
#define STAGE_BYTES 65536
#define OFF_AL 16384
#define OFF_BH 32768
#define OFF_BL 49152
#define SMEM_BYTES 131072

__device__ __forceinline__ void load_mat(const __nv_bfloat16* __restrict__ G,
                                         int ld, int rb, int k0,
                                         char* sdst, int tid) {
#pragma unroll
    for (int p = 0; p < 4; p++) {
        int idx = tid + p * 256;
        int row = idx >> 3, ch = idx & 7;
        uint4 v = *(const uint4*)(G + (size_t)(rb + row) * ld + k0 + ch * 8);
        *(uint4*)(sdst + row * 128 + ((ch ^ (row & 7)) << 4)) = v;
    }
}

// mode 0: v = s*acc (+bias[col]) (*rowmask)   mode 1: v = s*acc; colmask==0 -> -1e30
__global__ void __launch_bounds__(256, 1)
mma_gemm(const __nv_bfloat16* __restrict__ Ahi, const __nv_bfloat16* __restrict__ Alo,
         const __nv_bfloat16* __restrict__ A2hi, const __nv_bfloat16* __restrict__ A2lo,
         const __nv_bfloat16* __restrict__ Bhi, const __nv_bfloat16* __restrict__ Blo,
         float* __restrict__ C,
         const float* __restrict__ bias, const float* __restrict__ mask,
         float scaleMul, int scaleIdx,
         int K, int splitK, int lda, int lda2, int ldb, int ldc,
         int Hz, long zAb, long zAh, long zBb, long zBh, long zCb, long zCh, int zMb,
         int mode) {
    extern __shared__ char smem[];
    uint32_t sb = smem_u32(smem);
    int tid = threadIdx.x;
    int wid = tid >> 5, lane = tid & 31;

    int z = blockIdx.z;
    int zb = z / Hz, zh = z - zb * Hz;
    Ahi += (size_t)zb * zAb + (size_t)zh * zAh;
    Alo += (size_t)zb * zAb + (size_t)zh * zAh;
    if (A2hi) { A2hi += (size_t)zb * zAb + (size_t)zh * zAh; A2lo += (size_t)zb * zAb + (size_t)zh * zAh; }
    Bhi += (size_t)zb * zBb + (size_t)zh * zBh;
    Blo += (size_t)zb * zBb + (size_t)zh * zBh;
    C += (size_t)zb * zCb + (size_t)zh * zCh;
    size_t maskOff = (size_t)zb * (size_t)zMb;

    int rowBase = blockIdx.y * 128;
    int colBase = blockIdx.x * 128;
    int wm = wid & 1, wn = wid >> 1;  // warp tile rows wm*64, cols wn*32

    float acc[4][4][4];
#pragma unroll
    for (int i = 0; i < 4; i++)
#pragma unroll
        for (int j = 0; j < 4; j++)
#pragma unroll
            for (int q = 0; q < 4; q++) acc[i][j][q] = 0.f;

    // ldmatrix lane geometry
    // A frag f (m16): lanes 0-15 -> rows m0..15 (kchunk lo), lanes 16-31 -> same rows (kchunk hi)
    uint32_t aTerm[4];
    int aSw[4];
    int aK = lane >> 4;  // 0/1 within a k16 step
#pragma unroll
    for (int f = 0; f < 4; f++) {
        int r = wm * 64 + f * 16 + (lane & 15);
        aTerm[f] = (uint32_t)(r * 128);
        aSw[f] = r & 7;
    }
    // B x4 (n16 block nb): lanes 0-7 n0-7 k-lo, 8-15 n0-7 k-hi, 16-23 n8-15 k-lo, 24-31 n8-15 k-hi
    uint32_t bTerm[2];
    int bSw[2];
    int bK = (lane >> 3) & 1;
#pragma unroll
    for (int nb = 0; nb < 2; nb++) {
        int r = wn * 32 + nb * 16 + (lane & 7) + ((lane >> 4) << 3);
        bTerm[nb] = (uint32_t)(r * 128);
        bSw[nb] = r & 7;
    }

    int nIter = K >> 6;

    // prologue: stage 0
    {
        const __nv_bfloat16 *ah = Ahi, *al = Alo;
        int la = lda;
        char* sB = smem;
        load_mat(ah, la, rowBase, 0, sB, tid);
        load_mat(al, la, rowBase, 0, sB + OFF_AL, tid);
        load_mat(Bhi, ldb, colBase, 0, sB + OFF_BH, tid);
        load_mat(Blo, ldb, colBase, 0, sB + OFF_BL, tid);
    }

    for (int it = 0; it < nIter; it++) {
        __syncthreads();
        if (it + 1 < nIter) {
            int k0 = (it + 1) << 6;
            const __nv_bfloat16 *ah = Ahi, *al = Alo;
            int la = lda, kk = k0;
            if (A2hi && k0 >= splitK) { ah = A2hi; al = A2lo; la = lda2; kk = k0 - splitK; }
            char* sB = smem + ((it + 1) & 1) * STAGE_BYTES;
            load_mat(ah, la, rowBase, kk, sB, tid);
            load_mat(al, la, rowBase, kk, sB + OFF_AL, tid);
            load_mat(Bhi, ldb, colBase, k0, sB + OFF_BH, tid);
            load_mat(Blo, ldb, colBase, k0, sB + OFF_BL, tid);
        }
        uint32_t base = sb + (it & 1) * STAGE_BYTES;
#pragma unroll
        for (int ks = 0; ks < 4; ks++) {
            uint32_t ah[4][4], al[4][4], bh[4][2], bl[4][2];
            int kcA = ks * 2 + aK;
            int kcB = ks * 2 + bK;
#pragma unroll
            for (int f = 0; f < 4; f++) {
                uint32_t addr = base + aTerm[f] + (uint32_t)((kcA ^ aSw[f]) << 4);
                LDM4(ah[f][0], ah[f][1], ah[f][2], ah[f][3], addr);
                LDM4(al[f][0], al[f][1], al[f][2], al[f][3], addr + OFF_AL);
            }
#pragma unroll
            for (int nb = 0; nb < 2; nb++) {
                uint32_t addr = base + OFF_BH + bTerm[nb] + (uint32_t)((kcB ^ bSw[nb]) << 4);
                LDM4(bh[nb * 2][0], bh[nb * 2][1], bh[nb * 2 + 1][0], bh[nb * 2 + 1][1], addr);
                LDM4(bl[nb * 2][0], bl[nb * 2][1], bl[nb * 2 + 1][0], bl[nb * 2 + 1][1],
                     addr + (OFF_BL - OFF_BH));
            }
#pragma unroll
            for (int mi = 0; mi < 4; mi++)
#pragma unroll
                for (int nj = 0; nj < 4; nj++) {
                    MMA(acc[mi][nj], ah[mi], bh[nj]);
                    MMA(acc[mi][nj], ah[mi], bl[nj]);
                    MMA(acc[mi][nj], al[mi], bh[nj]);
                }
        }
    }

    // ---- epilogue: direct to gmem ----
    float s = scaleMul * (scaleIdx >= 0 ? d_scales[scaleIdx] : 1.0f);
    int r0 = rowBase + wm * 64 + (lane >> 2);
    int c0 = colBase + wn * 32 + (lane & 3) * 2;
#pragma unroll
    for (int nj = 0; nj < 4; nj++) {
        int c = c0 + nj * 8;
        float b0 = 0.f, b1 = 0.f, cm0 = 1.f, cm1 = 1.f;
        if (bias) { b0 = bias[c]; b1 = bias[c + 1]; }
        if (mode == 1) { cm0 = mask[maskOff + c]; cm1 = mask[maskOff + c + 1]; }
#pragma unroll
        for (int mi = 0; mi < 4; mi++) {
            int r = r0 + mi * 16;
            float v0 = acc[mi][nj][0] * s + b0;
            float v1 = acc[mi][nj][1] * s + b1;
            float v2 = acc[mi][nj][2] * s + b0;
            float v3 = acc[mi][nj][3] * s + b1;
            if (mode == 1) {
                if (cm0 == 0.f) { v0 = -1e30f; v2 = -1e30f; }
                if (cm1 == 0.f) { v1 = -1e30f; v3 = -1e30f; }
            } else if (mask) {
                float m0 = mask[maskOff + r];
                float m8 = mask[maskOff + r + 8];
                v0 *= m0; v1 *= m0; v2 *= m8; v3 *= m8;
            }
            *(float2*)(C + (size_t)r * ldc + c) = make_float2(v0, v1);
            *(float2*)(C + (size_t)(r + 8) * ldc + c) = make_float2(v2, v3);
        }
    }
}

// ======================= launch =======================
extern "C" void kernel_launch(void* const* d_in, const int* in_sizes, int n_in,
                              void* d_out, int out_size) {
    const float* src = (const float*)d_in[0];
    const float* tgt = (const float*)d_in[1];
    const float* src_mask = (const float*)d_in[2];
    const float* tgt_mask = (const float*)d_in[3];
    const float* v_src = (const float*)d_in[4];
    const float* g_src = (const float*)d_in[5];
    const float* b_src = (const float*)d_in[6];
    const float* v_tgt = (const float*)d_in[7];
    const float* g_tgt = (const float*)d_in[8];
    const float* b_tgt = (const float*)d_in[9];
    const float* v_out = (const float*)d_in[10];
    const float* g_out = (const float*)d_in[11];
    const float* b_out = (const float*)d_in[12];
    float* out = (float*)d_out;

    static int configured = 0;
    cudaFuncSetAttribute(mma_gemm, cudaFuncAttributeMaxDynamicSharedMemorySize, SMEM_BYTES);
    (void)configured;

#define SYM(T, p, s) T* p; { void* q; cudaGetSymbolAddress(&q, s); p = (T*)q; }
    SYM(float, st, d_st) SYM(float, tt, d_tt) SYM(float, sc, d_sc) SYM(float, tu, d_tu)
    SYM(__nv_bfloat16, srch, s_src_h) SYM(__nv_bfloat16, srcl, s_src_l)
    SYM(__nv_bfloat16, tgth, s_tgt_h) SYM(__nv_bfloat16, tgtl, s_tgt_l)
    SYM(__nv_bfloat16, vsh, s_vsrc_h) SYM(__nv_bfloat16, vsl, s_vsrc_l)
    SYM(__nv_bfloat16, vth, s_vtgt_h) SYM(__nv_bfloat16, vtl, s_vtgt_l)
    SYM(__nv_bfloat16, voh, s_vout_h) SYM(__nv_bfloat16, vol, s_vout_l)
    SYM(__nv_bfloat16, kh, s_key_h) SYM(__nv_bfloat16, kl, s_key_l)
    SYM(__nv_bfloat16, vvh, s_vt_h) SYM(__nv_bfloat16, vvl, s_vt_l)
    SYM(__nv_bfloat16, qh, s_q_h) SYM(__nv_bfloat16, ql, s_q_l)
    SYM(__nv_bfloat16, pph, s_p_h) SYM(__nv_bfloat16, ppl, s_p_l)
    SYM(__nv_bfloat16, tuh, s_tu_h) SYM(__nv_bfloat16, tul, s_tu_l)
#undef SYM

    const long TS = (long)512 * 1024;

    // scales
    sumsq_partial<<<dim3(256, 3), 256>>>(v_src, 2048 * 1024, v_tgt, 1024 * 1024, v_out, 1024 * 2048);
    finalize_scales<<<3, 256>>>(g_src, g_tgt, g_out);

    // input splits
    split2<<<dim3(1, 32768), 256>>>(src, srch, srcl, 256, 256);
    split2<<<dim3(1, 16384), 256>>>(tgt, tgth, tgtl, 256, 256);
    split2<<<dim3(1, 2048), 256>>>(v_src, vsh, vsl, 256, 256);
    split2<<<dim3(1, 1024), 256>>>(v_tgt, vth, vtl, 256, 256);
    split2<<<dim3(2, 1024), 256>>>(v_out, voh, vol, 512, 512);

    // GEMM1: src_trans = rowmask * (src @ (s0*v_src)^T + b_src)   [32768, 2048]
    mma_gemm<<<dim3(16, 256, 1), 256, SMEM_BYTES>>>(
        srch, srcl, nullptr, nullptr, vsh, vsl, st, b_src, src_mask,
        1.0f, 0, 1024, 0, 1024, 0, 1024, 2048,
        1, 0, 0, 0, 0, 0, 0, 0, 0);

    // key split (cols 0..1023 of st), valT split (cols 1024..2047, transposed)
    split2<<<dim3(1, 32768), 256>>>(st, kh, kl, 256, 512);
    splitValT<<<dim3(32, 32, 32), dim3(32, 8)>>>(st, vvh, vvl);

    // GEMM2: tgt_trans = rowmask * (tgt @ (s1*v_tgt)^T + b_tgt)   [16384, 1024]
    mma_gemm<<<dim3(8, 128, 1), 256, SMEM_BYTES>>>(
        tgth, tgtl, nullptr, nullptr, vth, vtl, tt, b_tgt, tgt_mask,
        1.0f, 1, 1024, 0, 1024, 0, 1024, 1024,
        1, 0, 0, 0, 0, 0, 0, 0, 0);

    split2<<<dim3(1, 16384), 256>>>(tt, qh, ql, 256, 256);

    // QK: scores[b,h,t,s] = (q @ k^T)/sqrt(128), colmask -> -1e30
    mma_gemm<<<dim3(8, 4, 256), 256, SMEM_BYTES>>>(
        qh, ql, nullptr, nullptr, kh, kl, sc, nullptr, src_mask,
        0.08838834764831845f, -1, 128, 0, 1024, 0, 1024, 1024,
        8, (long)512 * 1024, 128, (long)1024 * 1024, 128, 8 * TS, TS, 1024, 1);

    // softmax + split P
    softmax_split<<<131072 / 8, 256>>>(sc, pph, ppl);

    // PV: tgt_update[b,t,h*128+d] = P[b,h,t,:] @ Vt[b,h,d,:]^T
    mma_gemm<<<dim3(1, 4, 256), 256, SMEM_BYTES>>>(
        pph, ppl, nullptr, nullptr, vvh, vvl, tu, nullptr, nullptr,
        1.0f, -1, 1024, 0, 1024, 0, 1024, 1024,
        8, 8 * TS, TS, (long)1024 * 1024, (long)128 * 1024, (long)512 * 1024, 128, 0, 0);

    split2<<<dim3(1, 16384), 256>>>(tu, tuh, tul, 256, 256);

    // GEMM3: out = [tgt | tgt_update] @ (s2*v_out)^T + b_out   [16384, 1024]
    mma_gemm<<<dim3(8, 128, 1), 256, SMEM_BYTES>>>(
        tgth, tgtl, tuh, tul, voh, vol, out, b_out, nullptr,
        1.0f, 2, 2048, 1024, 1024, 1024, 2048, 1024,
        1, 0, 0, 0, 0, 0, 0, 0, 0);
}